// round 14
// baseline (speedup 1.0000x reference)
#include <cuda_runtime.h>

#define NN   25000
#define EE0  400000
#define EEL  425000
#define DD   64
#define HH   4
#define CC   64
#define HCX  256
#define LLAY 3
#define NEG  0.2f
#define EPSN 1e-5f

#define CNT_BLKS 1661            // ceil(EEL/256)
#define TRN_BLKS 192             // LLAY*HCX*DD / 256
#define PROJ_BLKS 1250           // NN / NB

// ---------------- scratch (static device globals; no allocation) ----------------
__device__ float4 g_xl[NN * 64];              // [N][H*C] as float4  (25.6 MB)
__device__ float4 g_xr[NN * 64];              // 25.6 MB
__device__ float  g_h[NN * CC];               // per-layer conv output (pre-norm)
__device__ int    g_rowptr[NN + 1];
__device__ int    g_woff[NN];
__device__ int    g_deg[NN];                  // zero at start of every call (self-cleaning)
__device__ int    g_csrsrc[EEL];
__device__ float  g_colsum[LLAY * CC], g_colsq[LLAY * CC];   // self-cleaning
__device__ float  g_A[LLAY * CC], g_B[LLAY * CC];            // per-layer norm affine
__device__ float  g_WlT[LLAY * DD * HCX];     // transposed weights [l][d][o]
__device__ float  g_WrT[LLAY * DD * HCX];

// ---------------- per-warp dtype sniff: int64 edge_index has zero odd words ----------------
__device__ __forceinline__ int sniff_is64(const int* __restrict__ ei) {
    int lane = threadIdx.x & 31;
    int v = ei[2 * lane + 1] | ei[2 * (lane + 32) + 1];
    v = __reduce_or_sync(0xffffffffu, v);
    return v == 0;
}

// ---------------- k_pre: fused degree-count + weight-transpose (block ranges) ----------------
__global__ __launch_bounds__(256) void k_pre(const int* __restrict__ ei,
                                             const float* __restrict__ Wl,
                                             const float* __restrict__ Wr) {
    int bid = blockIdx.x;
    int tid = threadIdx.x;
    if (bid < CNT_BLKS) {
        int is64 = sniff_is64(ei);
        int e = bid * 256 + tid;
        if (e >= EEL) return;
        int dst = (e < EE0) ? (is64 ? ei[2 * (EE0 + e)] : ei[EE0 + e]) : (e - EE0);
        if ((unsigned)dst < (unsigned)NN)
            atomicAdd(&g_deg[dst], 1);
    } else {
        int idx = (bid - CNT_BLKS) * 256 + tid;
        int tot = LLAY * HCX * DD;
        if (idx >= tot) return;
        int l = idx / (HCX * DD);
        int r = idx - l * (HCX * DD);
        int o = r / DD;
        int d = r - o * DD;
        g_WlT[l * HCX * DD + d * HCX + o] = Wl[idx];
        g_WrT[l * HCX * DD + d * HCX + o] = Wr[idx];
    }
}

// ---------------- scan (re-zeros g_deg for the next call) ----------------
__global__ __launch_bounds__(1024) void k_scan() {
    __shared__ int sp[1024];
    int i = threadIdx.x;
    const int CH = 25;                   // 1024*25 = 25600 >= 25000
    int beg = i * CH;
    int end = beg + CH; if (end > NN) end = NN;
    int s = 0;
    for (int j = beg; j < end; ++j) s += g_deg[j];
    sp[i] = s;
    __syncthreads();
    for (int off = 1; off < 1024; off <<= 1) {
        int v = (i >= off) ? sp[i - off] : 0;
        __syncthreads();
        sp[i] += v;
        __syncthreads();
    }
    int run = sp[i] - s;                 // exclusive prefix
    for (int j = beg; j < end; ++j) {
        g_rowptr[j] = run;
        g_woff[j]   = run;
        run += g_deg[j];
    }
    for (int j = beg; j < end; ++j) g_deg[j] = 0;   // self-clean for next replay
    if (i == 0) g_rowptr[NN] = EEL;
}

// ---------------- projection body (norm of previous layer fused into the load) ----------------
#define NB 20
__device__ __forceinline__ void proj_body(int vbid,
                                          const float* __restrict__ xext,
                                          const float* __restrict__ bl,
                                          const float* __restrict__ br,
                                          int l) {
    __shared__ float4 xs4[NB * 16];                // [n][d4], 5 KB
    int node0 = vbid * NB;                         // 25000 % 20 == 0
    int tid = threadIdx.x;
    if (l == 0) {
        const float4* xp = (const float4*)(xext + node0 * DD);
        for (int i = tid; i < NB * 16; i += 256)
            xs4[i] = xp[i];
    } else {
        const float4* Ap = (const float4*)(g_A + (l - 1) * CC);
        const float4* Bp = (const float4*)(g_B + (l - 1) * CC);
        const float4* hp = (const float4*)(g_h + node0 * DD);
        for (int i = tid; i < NB * 16; i += 256) {
            int d4 = i & 15;                       // DD/4 == 16
            float4 A = Ap[d4], B = Bp[d4], v = hp[i];
            float4 o;
            o.x = fmaf(v.x, A.x, B.x);
            o.y = fmaf(v.y, A.y, B.y);
            o.z = fmaf(v.z, A.z, B.z);
            o.w = fmaf(v.w, A.w, B.w);
            xs4[i] = o;
        }
    }
    __syncthreads();

    const float* wl = g_WlT + l * DD * HCX;
    const float* wr = g_WrT + l * DD * HCX;
    float accl[NB], accr[NB];
#pragma unroll
    for (int n = 0; n < NB; ++n) { accl[n] = 0.f; accr[n] = 0.f; }

#pragma unroll 4
    for (int d4 = 0; d4 < 16; ++d4) {
        float wa0 = wl[(4 * d4 + 0) * HCX + tid];
        float wa1 = wl[(4 * d4 + 1) * HCX + tid];
        float wa2 = wl[(4 * d4 + 2) * HCX + tid];
        float wa3 = wl[(4 * d4 + 3) * HCX + tid];
        float wb0 = wr[(4 * d4 + 0) * HCX + tid];
        float wb1 = wr[(4 * d4 + 1) * HCX + tid];
        float wb2 = wr[(4 * d4 + 2) * HCX + tid];
        float wb3 = wr[(4 * d4 + 3) * HCX + tid];
#pragma unroll
        for (int n = 0; n < NB; ++n) {
            float4 xv = xs4[n * 16 + d4];          // one LDS.128 broadcast
            float al = accl[n], ar = accr[n];
            al = fmaf(wa0, xv.x, al);
            al = fmaf(wa1, xv.y, al);
            al = fmaf(wa2, xv.z, al);
            al = fmaf(wa3, xv.w, al);
            ar = fmaf(wb0, xv.x, ar);
            ar = fmaf(wb1, xv.y, ar);
            ar = fmaf(wb2, xv.z, ar);
            ar = fmaf(wb3, xv.w, ar);
            accl[n] = al; accr[n] = ar;
        }
    }
    float bli = bl[l * HCX + tid], bri = br[l * HCX + tid];
    float* xlp = (float*)g_xl;
    float* xrp = (float*)g_xr;
#pragma unroll
    for (int n = 0; n < NB; ++n) {
        int node = node0 + n;
        xlp[node * HCX + tid] = accl[n] + bli;
        xrp[node * HCX + tid] = accr[n] + bri;
    }
}

// ---------------- k_mid: fused CSR-scatter + proj layer 0 (block ranges) ----------------
__global__ __launch_bounds__(256) void k_mid(const int* __restrict__ ei,
                                             const float* __restrict__ xext,
                                             const float* __restrict__ bl,
                                             const float* __restrict__ br) {
    int bid = blockIdx.x;
    if (bid < CNT_BLKS) {
        int is64 = sniff_is64(ei);
        int e = bid * 256 + threadIdx.x;
        if (e >= EEL) return;
        int src, dst;
        if (e < EE0) {
            if (is64) { src = ei[2 * e]; dst = ei[2 * (EE0 + e)]; }
            else      { src = ei[e];     dst = ei[EE0 + e]; }
        } else {
            src = dst = e - EE0;
        }
        if ((unsigned)dst >= (unsigned)NN || (unsigned)src >= (unsigned)NN) return;
        int pos = atomicAdd(&g_woff[dst], 1);
        g_csrsrc[pos] = src;
    } else {
        proj_body(bid - CNT_BLKS, xext, bl, br, 0);
    }
}

// ---------------- standalone proj for layers >= 1 ----------------
__global__ __launch_bounds__(256) void k_proj(const float* __restrict__ xext,
                                              const float* __restrict__ bl,
                                              const float* __restrict__ br,
                                              int l) {
    proj_body(blockIdx.x, xext, bl, br, l);
}

// ---------------- fused GAT (unchanged from best-known 516us version) ----------------
__device__ __forceinline__ float lrelu(float v) { return v > 0.f ? v : NEG * v; }

__global__ __launch_bounds__(256) void k_gat(const float* __restrict__ att,
                                             const float* __restrict__ cbias,
                                             int l) {
    int node = blockIdx.x;
    int tid  = threadIdx.x;
    int lane = tid & 31;
    int w    = tid >> 5;
    int row0 = g_rowptr[node];
    int deg  = g_rowptr[node + 1] - row0;

    __shared__ float  s_d[32];          // [warp][head] partial denominators
    __shared__ float4 s_acc4[8 * 64];   // per-warp channel accumulators (8 KB)
    __shared__ float  s_red[256];

    const float4* att4 = (const float4*)(att + l * HCX);
    float4 at0 = att4[lane * 2];
    float4 at1 = att4[lane * 2 + 1];
    float4 xr0 = g_xr[node * 64 + lane * 2];
    float4 xr1 = g_xr[node * 64 + lane * 2 + 1];

    float den = 0.f;
    float acc[8];
#pragma unroll
    for (int j = 0; j < 8; ++j) acc[j] = 0.f;

    for (int k = w; k < deg; k += 8) {
        int s = g_csrsrc[row0 + k];
        float4 a0 = g_xl[s * 64 + lane * 2];
        float4 a1 = g_xl[s * 64 + lane * 2 + 1];
        float p = 0.f;
        p = fmaf(at0.x, lrelu(a0.x + xr0.x), p);
        p = fmaf(at0.y, lrelu(a0.y + xr0.y), p);
        p = fmaf(at0.z, lrelu(a0.z + xr0.z), p);
        p = fmaf(at0.w, lrelu(a0.w + xr0.w), p);
        p = fmaf(at1.x, lrelu(a1.x + xr1.x), p);
        p = fmaf(at1.y, lrelu(a1.y + xr1.y), p);
        p = fmaf(at1.z, lrelu(a1.z + xr1.z), p);
        p = fmaf(at1.w, lrelu(a1.w + xr1.w), p);
        p += __shfl_xor_sync(0xffffffffu, p, 1);
        p += __shfl_xor_sync(0xffffffffu, p, 2);
        p += __shfl_xor_sync(0xffffffffu, p, 4);
        float wgt = __expf(p);         // softmax-shift-free: |p| bounded ~10
        den += wgt;
        acc[0] = fmaf(wgt, a0.x, acc[0]);
        acc[1] = fmaf(wgt, a0.y, acc[1]);
        acc[2] = fmaf(wgt, a0.z, acc[2]);
        acc[3] = fmaf(wgt, a0.w, acc[3]);
        acc[4] = fmaf(wgt, a1.x, acc[4]);
        acc[5] = fmaf(wgt, a1.y, acc[5]);
        acc[6] = fmaf(wgt, a1.z, acc[6]);
        acc[7] = fmaf(wgt, a1.w, acc[7]);
    }

    int h = lane >> 3;
    if ((lane & 7) == 0) s_d[w * 4 + h] = den;
    s_acc4[w * 64 + lane * 2]     = make_float4(acc[0], acc[1], acc[2], acc[3]);
    s_acc4[w * 64 + lane * 2 + 1] = make_float4(acc[4], acc[5], acc[6], acc[7]);
    __syncthreads();

    const float* sa = (const float*)s_acc4;      // [w][256] channel-major view
    int hh = tid >> 6;
    float num = 0.f, D = 0.f;
#pragma unroll
    for (int ww = 0; ww < 8; ++ww) {
        num += sa[ww * 256 + tid];
        D   += s_d[ww * 4 + hh];
    }
    s_red[tid] = num / D;
    __syncthreads();
    if (tid < 64) {
        float sum = s_red[tid] + s_red[tid + 64] + s_red[tid + 128] + s_red[tid + 192];
        g_h[node * CC + tid] = 0.25f * sum + cbias[l * CC + tid];
    }
}

// ---------------- GraphNorm stats (float4) ----------------
__global__ __launch_bounds__(256) void k_colstats(int l) {
    int tid = threadIdx.x;
    const float4* hp = (const float4*)g_h;
    float4 s = make_float4(0.f, 0.f, 0.f, 0.f);
    float4 q = make_float4(0.f, 0.f, 0.f, 0.f);
    int stride = gridDim.x * blockDim.x;                 // multiple of 16
    for (int idx = blockIdx.x * blockDim.x + tid; idx < NN * 16; idx += stride) {
        float4 v = hp[idx];
        s.x += v.x; s.y += v.y; s.z += v.z; s.w += v.w;
        q.x = fmaf(v.x, v.x, q.x); q.y = fmaf(v.y, v.y, q.y);
        q.z = fmaf(v.z, v.z, q.z); q.w = fmaf(v.w, v.w, q.w);
    }
    __shared__ float4 ss[256], sq[256];
    ss[tid] = s; sq[tid] = q;
    __syncthreads();
    for (int off = 128; off >= 16; off >>= 1) {
        if (tid < off) {
            float4 a = ss[tid], b = ss[tid + off];
            a.x += b.x; a.y += b.y; a.z += b.z; a.w += b.w;
            ss[tid] = a;
            float4 c = sq[tid], d = sq[tid + off];
            c.x += d.x; c.y += d.y; c.z += d.z; c.w += d.w;
            sq[tid] = c;
        }
        __syncthreads();
    }
    if (tid < 16) {
        float4 a = ss[tid], c = sq[tid];
        float* cs = g_colsum + l * CC + tid * 4;
        float* cq = g_colsq  + l * CC + tid * 4;
        atomicAdd(&cs[0], a.x); atomicAdd(&cs[1], a.y);
        atomicAdd(&cs[2], a.z); atomicAdd(&cs[3], a.w);
        atomicAdd(&cq[0], c.x); atomicAdd(&cq[1], c.y);
        atomicAdd(&cq[2], c.z); atomicAdd(&cq[3], c.w);
    }
}

// ---------------- finalize (re-zeros its layer's stats for the next call) ----------------
__global__ void k_finalize(const float* __restrict__ gw,
                           const float* __restrict__ gs,
                           const float* __restrict__ gb, int l) {
    int c = threadIdx.x;
    if (c >= CC) return;
    float invn = 1.0f / (float)NN;
    float mu = g_colsum[l * CC + c] * invn;
    float m2 = g_colsq[l * CC + c]  * invn;
    g_colsum[l * CC + c] = 0.f;          // self-clean for next replay
    g_colsq[l * CC + c]  = 0.f;
    float sc = gs[l * CC + c];
    float var = m2 - 2.f * sc * mu * mu + sc * sc * mu * mu;
    float rstd = rsqrtf(var + EPSN);
    float A = rstd * gw[l * CC + c];
    g_A[l * CC + c] = A;
    g_B[l * CC + c] = gb[l * CC + c] - sc * mu * A;
}

__global__ __launch_bounds__(256) void k_norm(float* __restrict__ out) {
    const float4* Ap = (const float4*)(g_A + (LLAY - 1) * CC);
    const float4* Bp = (const float4*)(g_B + (LLAY - 1) * CC);
    const float4* hp = (const float4*)g_h;
    float4* op = (float4*)out;
    int stride = gridDim.x * blockDim.x;
    for (int idx = blockIdx.x * blockDim.x + threadIdx.x; idx < NN * 16; idx += stride) {
        int c4 = idx & 15;
        float4 A = Ap[c4], B = Bp[c4], v = hp[idx];
        float4 o;
        o.x = fmaf(v.x, A.x, B.x);
        o.y = fmaf(v.y, A.y, B.y);
        o.z = fmaf(v.z, A.z, B.z);
        o.w = fmaf(v.w, A.w, B.w);
        op[idx] = o;
    }
}

// ---------------- launch ----------------
extern "C" void kernel_launch(void* const* d_in, const int* in_sizes, int n_in,
                              void* d_out, int out_size) {
    const float* x   = (const float*)d_in[0];
    const int*   ei  = (const int*)d_in[1];
    const float* Wl  = (const float*)d_in[2];
    const float* bl  = (const float*)d_in[3];
    const float* Wr  = (const float*)d_in[4];
    const float* br  = (const float*)d_in[5];
    const float* att = (const float*)d_in[6];
    const float* cb  = (const float*)d_in[7];
    const float* gw  = (const float*)d_in[8];
    const float* gs  = (const float*)d_in[9];
    const float* gb  = (const float*)d_in[10];
    float* out = (float*)d_out;

    k_pre<<<CNT_BLKS + TRN_BLKS, 256>>>(ei, Wl, Wr);           // 0: count + transpose
    k_scan<<<1, 1024>>>();                                     // 1: rowptr (+deg re-zero)
    k_mid<<<CNT_BLKS + PROJ_BLKS, 256>>>(ei, x, bl, br);       // 2: scatter + proj layer 0
    k_gat<<<NN, 256>>>(att, cb, 0);                            // 3: <- PROFILED
    k_colstats<<<296, 256>>>(0);
    k_finalize<<<1, 64>>>(gw, gs, gb, 0);

    for (int l = 1; l < LLAY; ++l) {
        k_proj<<<PROJ_BLKS, 256>>>(x, bl, br, l);
        k_gat<<<NN, 256>>>(att, cb, l);
        k_colstats<<<296, 256>>>(l);
        k_finalize<<<1, 64>>>(gw, gs, gb, l);
    }
    k_norm<<<296, 256>>>(out);
}

// round 17
// speedup vs baseline: 1.3610x; 1.3610x over previous
#include <cuda_runtime.h>

#define NN   25000
#define EE0  400000
#define EEL  425000
#define DD   64
#define HH   4
#define CC   64
#define HCX  256
#define LLAY 3
#define NEG  0.2f
#define EPSN 1e-5f

#define CNT_BLKS 1661            // ceil(EEL/256)
#define TRN_BLKS 192             // LLAY*HCX*DD / 256
#define PROJ_BLKS 1250           // NN / NB

// ---------------- scratch (static device globals; no allocation) ----------------
__device__ float4 g_xl[NN * 64];              // [N][H*C] as float4  (25.6 MB)
__device__ float4 g_xr[NN * 64];              // 25.6 MB
__device__ float  g_h[NN * CC];               // per-layer conv output (pre-norm)
__device__ int    g_rowptr[NN + 1];
__device__ int    g_woff[NN];
__device__ int    g_deg[NN];                  // zero at start of every call (self-cleaning)
__device__ int    g_csrsrc[EEL];
__device__ float  g_colsum[LLAY * CC], g_colsq[LLAY * CC];   // self-cleaning
__device__ float  g_A[LLAY * CC], g_B[LLAY * CC];            // per-layer norm affine
__device__ float  g_WlT[LLAY * DD * HCX];     // transposed weights [l][d][o]
__device__ float  g_WrT[LLAY * DD * HCX];

// ---------------- per-warp dtype sniff: int64 edge_index has zero odd words ----------------
__device__ __forceinline__ int sniff_is64(const int* __restrict__ ei) {
    int lane = threadIdx.x & 31;
    int v = ei[2 * lane + 1] | ei[2 * (lane + 32) + 1];
    v = __reduce_or_sync(0xffffffffu, v);
    return v == 0;
}

// ---------------- k_pre: fused degree-count + weight-transpose (block ranges) ----------------
__global__ __launch_bounds__(256) void k_pre(const int* __restrict__ ei,
                                             const float* __restrict__ Wl,
                                             const float* __restrict__ Wr) {
    int bid = blockIdx.x;
    int tid = threadIdx.x;
    if (bid < CNT_BLKS) {
        int is64 = sniff_is64(ei);
        int e = bid * 256 + tid;
        if (e >= EEL) return;
        int dst = (e < EE0) ? (is64 ? ei[2 * (EE0 + e)] : ei[EE0 + e]) : (e - EE0);
        if ((unsigned)dst < (unsigned)NN)
            atomicAdd(&g_deg[dst], 1);
    } else {
        int idx = (bid - CNT_BLKS) * 256 + tid;
        int tot = LLAY * HCX * DD;
        if (idx >= tot) return;
        int l = idx / (HCX * DD);
        int r = idx - l * (HCX * DD);
        int o = r / DD;
        int d = r - o * DD;
        g_WlT[l * HCX * DD + d * HCX + o] = Wl[idx];
        g_WrT[l * HCX * DD + d * HCX + o] = Wr[idx];
    }
}

// ---------------- scan (re-zeros g_deg for the next call) ----------------
__global__ __launch_bounds__(1024) void k_scan() {
    __shared__ int sp[1024];
    int i = threadIdx.x;
    const int CH = 25;                   // 1024*25 = 25600 >= 25000
    int beg = i * CH;
    int end = beg + CH; if (end > NN) end = NN;
    int s = 0;
    for (int j = beg; j < end; ++j) s += g_deg[j];
    sp[i] = s;
    __syncthreads();
    for (int off = 1; off < 1024; off <<= 1) {
        int v = (i >= off) ? sp[i - off] : 0;
        __syncthreads();
        sp[i] += v;
        __syncthreads();
    }
    int run = sp[i] - s;                 // exclusive prefix
    for (int j = beg; j < end; ++j) {
        g_rowptr[j] = run;
        g_woff[j]   = run;
        run += g_deg[j];
    }
    for (int j = beg; j < end; ++j) g_deg[j] = 0;   // self-clean for next replay
    if (i == 0) g_rowptr[NN] = EEL;
}

// ---------------- projection body (norm of previous layer fused into the load) ----------------
#define NB 20
__device__ __forceinline__ void proj_body(int vbid,
                                          const float* __restrict__ xext,
                                          const float* __restrict__ bl,
                                          const float* __restrict__ br,
                                          int l) {
    __shared__ float4 xs4[NB * 16];                // [n][d4], 5 KB
    int node0 = vbid * NB;                         // 25000 % 20 == 0
    int tid = threadIdx.x;
    if (l == 0) {
        const float4* xp = (const float4*)(xext + node0 * DD);
        for (int i = tid; i < NB * 16; i += 256)
            xs4[i] = xp[i];
    } else {
        const float4* Ap = (const float4*)(g_A + (l - 1) * CC);
        const float4* Bp = (const float4*)(g_B + (l - 1) * CC);
        const float4* hp = (const float4*)(g_h + node0 * DD);
        for (int i = tid; i < NB * 16; i += 256) {
            int d4 = i & 15;                       // DD/4 == 16
            float4 A = Ap[d4], B = Bp[d4], v = hp[i];
            float4 o;
            o.x = fmaf(v.x, A.x, B.x);
            o.y = fmaf(v.y, A.y, B.y);
            o.z = fmaf(v.z, A.z, B.z);
            o.w = fmaf(v.w, A.w, B.w);
            xs4[i] = o;
        }
    }
    __syncthreads();

    const float* wl = g_WlT + l * DD * HCX;
    const float* wr = g_WrT + l * DD * HCX;
    float accl[NB], accr[NB];
#pragma unroll
    for (int n = 0; n < NB; ++n) { accl[n] = 0.f; accr[n] = 0.f; }

#pragma unroll 4
    for (int d4 = 0; d4 < 16; ++d4) {
        float wa0 = wl[(4 * d4 + 0) * HCX + tid];
        float wa1 = wl[(4 * d4 + 1) * HCX + tid];
        float wa2 = wl[(4 * d4 + 2) * HCX + tid];
        float wa3 = wl[(4 * d4 + 3) * HCX + tid];
        float wb0 = wr[(4 * d4 + 0) * HCX + tid];
        float wb1 = wr[(4 * d4 + 1) * HCX + tid];
        float wb2 = wr[(4 * d4 + 2) * HCX + tid];
        float wb3 = wr[(4 * d4 + 3) * HCX + tid];
#pragma unroll
        for (int n = 0; n < NB; ++n) {
            float4 xv = xs4[n * 16 + d4];          // one LDS.128 broadcast
            float al = accl[n], ar = accr[n];
            al = fmaf(wa0, xv.x, al);
            al = fmaf(wa1, xv.y, al);
            al = fmaf(wa2, xv.z, al);
            al = fmaf(wa3, xv.w, al);
            ar = fmaf(wb0, xv.x, ar);
            ar = fmaf(wb1, xv.y, ar);
            ar = fmaf(wb2, xv.z, ar);
            ar = fmaf(wb3, xv.w, ar);
            accl[n] = al; accr[n] = ar;
        }
    }
    float bli = bl[l * HCX + tid], bri = br[l * HCX + tid];
    float* xlp = (float*)g_xl;
    float* xrp = (float*)g_xr;
#pragma unroll
    for (int n = 0; n < NB; ++n) {
        int node = node0 + n;
        xlp[node * HCX + tid] = accl[n] + bli;
        xrp[node * HCX + tid] = accr[n] + bri;
    }
}

// ---------------- k_mid: fused CSR-scatter + proj layer 0 (block ranges) ----------------
__global__ __launch_bounds__(256) void k_mid(const int* __restrict__ ei,
                                             const float* __restrict__ xext,
                                             const float* __restrict__ bl,
                                             const float* __restrict__ br) {
    int bid = blockIdx.x;
    if (bid < CNT_BLKS) {
        int is64 = sniff_is64(ei);
        int e = bid * 256 + threadIdx.x;
        if (e >= EEL) return;
        int src, dst;
        if (e < EE0) {
            if (is64) { src = ei[2 * e]; dst = ei[2 * (EE0 + e)]; }
            else      { src = ei[e];     dst = ei[EE0 + e]; }
        } else {
            src = dst = e - EE0;
        }
        if ((unsigned)dst >= (unsigned)NN || (unsigned)src >= (unsigned)NN) return;
        int pos = atomicAdd(&g_woff[dst], 1);
        g_csrsrc[pos] = src;
    } else {
        proj_body(bid - CNT_BLKS, xext, bl, br, 0);
    }
}

// ---------------- standalone proj for layers >= 1 ----------------
__global__ __launch_bounds__(256) void k_proj(const float* __restrict__ xext,
                                              const float* __restrict__ bl,
                                              const float* __restrict__ br,
                                              int l) {
    proj_body(blockIdx.x, xext, bl, br, l);
}

// ---------------- fused GAT: WARP per node, shift-free softmax, no smem ----------------
__device__ __forceinline__ float lrelu(float v) { return v > 0.f ? v : NEG * v; }

__global__ __launch_bounds__(256) void k_gat(const float* __restrict__ att,
                                             const float* __restrict__ cbias,
                                             int l) {
    int tid  = threadIdx.x;
    int lane = tid & 31;
    int w    = tid >> 5;
    int node = blockIdx.x * 8 + w;           // 3125 blocks * 8 warps = 25000
    int row0 = g_rowptr[node];
    int deg  = g_rowptr[node + 1] - row0;

    const float4* att4 = (const float4*)(att + l * HCX);
    float4 at0 = att4[lane * 2];
    float4 at1 = att4[lane * 2 + 1];
    float4 xr0 = g_xr[node * 64 + lane * 2];
    float4 xr1 = g_xr[node * 64 + lane * 2 + 1];

    float den = 0.f;
    float acc[8];
#pragma unroll
    for (int j = 0; j < 8; ++j) acc[j] = 0.f;

    // ~17 independent iterations per warp: gather -> logit -> exp -> accumulate.
    // No loop-carried chain except 4-cyc FMA accumulation (shift-free softmax).
#pragma unroll 2
    for (int k = 0; k < deg; ++k) {
        int s = g_csrsrc[row0 + k];
        float4 a0 = g_xl[s * 64 + lane * 2];
        float4 a1 = g_xl[s * 64 + lane * 2 + 1];
        float p = 0.f;
        p = fmaf(at0.x, lrelu(a0.x + xr0.x), p);
        p = fmaf(at0.y, lrelu(a0.y + xr0.y), p);
        p = fmaf(at0.z, lrelu(a0.z + xr0.z), p);
        p = fmaf(at0.w, lrelu(a0.w + xr0.w), p);
        p = fmaf(at1.x, lrelu(a1.x + xr1.x), p);
        p = fmaf(at1.y, lrelu(a1.y + xr1.y), p);
        p = fmaf(at1.z, lrelu(a1.z + xr1.z), p);
        p = fmaf(at1.w, lrelu(a1.w + xr1.w), p);
        p += __shfl_xor_sync(0xffffffffu, p, 1);
        p += __shfl_xor_sync(0xffffffffu, p, 2);
        p += __shfl_xor_sync(0xffffffffu, p, 4);
        float wgt = __expf(p);               // |p| bounded ~10: shift-free is exact-safe
        den += wgt;
        acc[0] = fmaf(wgt, a0.x, acc[0]);
        acc[1] = fmaf(wgt, a0.y, acc[1]);
        acc[2] = fmaf(wgt, a0.z, acc[2]);
        acc[3] = fmaf(wgt, a0.w, acc[3]);
        acc[4] = fmaf(wgt, a1.x, acc[4]);
        acc[5] = fmaf(wgt, a1.y, acc[5]);
        acc[6] = fmaf(wgt, a1.z, acc[6]);
        acc[7] = fmaf(wgt, a1.w, acc[7]);
    }

    // normalize per head (den uniform within 8-lane head group), then head-sum via shfl
    float inv = 1.0f / den;
#pragma unroll
    for (int j = 0; j < 8; ++j) {
        float v = acc[j] * inv;
        v += __shfl_xor_sync(0xffffffffu, v, 8);
        v += __shfl_xor_sync(0xffffffffu, v, 16);
        acc[j] = v;                          // lane L: sum over heads for c=(L&7)*8+j
    }
    if (lane < 8) {
        const float* cb = cbias + l * CC + lane * 8;
        float4 o0, o1;
        o0.x = 0.25f * acc[0] + cb[0];
        o0.y = 0.25f * acc[1] + cb[1];
        o0.z = 0.25f * acc[2] + cb[2];
        o0.w = 0.25f * acc[3] + cb[3];
        o1.x = 0.25f * acc[4] + cb[4];
        o1.y = 0.25f * acc[5] + cb[5];
        o1.z = 0.25f * acc[6] + cb[6];
        o1.w = 0.25f * acc[7] + cb[7];
        float4* hp = (float4*)(g_h + node * CC + lane * 8);
        hp[0] = o0;
        hp[1] = o1;
    }
}

// ---------------- GraphNorm stats (float4) ----------------
__global__ __launch_bounds__(256) void k_colstats(int l) {
    int tid = threadIdx.x;
    const float4* hp = (const float4*)g_h;
    float4 s = make_float4(0.f, 0.f, 0.f, 0.f);
    float4 q = make_float4(0.f, 0.f, 0.f, 0.f);
    int stride = gridDim.x * blockDim.x;                 // multiple of 16
    for (int idx = blockIdx.x * blockDim.x + tid; idx < NN * 16; idx += stride) {
        float4 v = hp[idx];
        s.x += v.x; s.y += v.y; s.z += v.z; s.w += v.w;
        q.x = fmaf(v.x, v.x, q.x); q.y = fmaf(v.y, v.y, q.y);
        q.z = fmaf(v.z, v.z, q.z); q.w = fmaf(v.w, v.w, q.w);
    }
    __shared__ float4 ss[256], sq[256];
    ss[tid] = s; sq[tid] = q;
    __syncthreads();
    for (int off = 128; off >= 16; off >>= 1) {
        if (tid < off) {
            float4 a = ss[tid], b = ss[tid + off];
            a.x += b.x; a.y += b.y; a.z += b.z; a.w += b.w;
            ss[tid] = a;
            float4 c = sq[tid], d = sq[tid + off];
            c.x += d.x; c.y += d.y; c.z += d.z; c.w += d.w;
            sq[tid] = c;
        }
        __syncthreads();
    }
    if (tid < 16) {
        float4 a = ss[tid], c = sq[tid];
        float* cs = g_colsum + l * CC + tid * 4;
        float* cq = g_colsq  + l * CC + tid * 4;
        atomicAdd(&cs[0], a.x); atomicAdd(&cs[1], a.y);
        atomicAdd(&cs[2], a.z); atomicAdd(&cs[3], a.w);
        atomicAdd(&cq[0], c.x); atomicAdd(&cq[1], c.y);
        atomicAdd(&cq[2], c.z); atomicAdd(&cq[3], c.w);
    }
}

// ---------------- finalize (re-zeros its layer's stats for the next call) ----------------
__global__ void k_finalize(const float* __restrict__ gw,
                           const float* __restrict__ gs,
                           const float* __restrict__ gb, int l) {
    int c = threadIdx.x;
    if (c >= CC) return;
    float invn = 1.0f / (float)NN;
    float mu = g_colsum[l * CC + c] * invn;
    float m2 = g_colsq[l * CC + c]  * invn;
    g_colsum[l * CC + c] = 0.f;          // self-clean for next replay
    g_colsq[l * CC + c]  = 0.f;
    float sc = gs[l * CC + c];
    float var = m2 - 2.f * sc * mu * mu + sc * sc * mu * mu;
    float rstd = rsqrtf(var + EPSN);
    float A = rstd * gw[l * CC + c];
    g_A[l * CC + c] = A;
    g_B[l * CC + c] = gb[l * CC + c] - sc * mu * A;
}

__global__ __launch_bounds__(256) void k_norm(float* __restrict__ out) {
    const float4* Ap = (const float4*)(g_A + (LLAY - 1) * CC);
    const float4* Bp = (const float4*)(g_B + (LLAY - 1) * CC);
    const float4* hp = (const float4*)g_h;
    float4* op = (float4*)out;
    int stride = gridDim.x * blockDim.x;
    for (int idx = blockIdx.x * blockDim.x + threadIdx.x; idx < NN * 16; idx += stride) {
        int c4 = idx & 15;
        float4 A = Ap[c4], B = Bp[c4], v = hp[idx];
        float4 o;
        o.x = fmaf(v.x, A.x, B.x);
        o.y = fmaf(v.y, A.y, B.y);
        o.z = fmaf(v.z, A.z, B.z);
        o.w = fmaf(v.w, A.w, B.w);
        op[idx] = o;
    }
}

// ---------------- launch ----------------
extern "C" void kernel_launch(void* const* d_in, const int* in_sizes, int n_in,
                              void* d_out, int out_size) {
    const float* x   = (const float*)d_in[0];
    const int*   ei  = (const int*)d_in[1];
    const float* Wl  = (const float*)d_in[2];
    const float* bl  = (const float*)d_in[3];
    const float* Wr  = (const float*)d_in[4];
    const float* br  = (const float*)d_in[5];
    const float* att = (const float*)d_in[6];
    const float* cb  = (const float*)d_in[7];
    const float* gw  = (const float*)d_in[8];
    const float* gs  = (const float*)d_in[9];
    const float* gb  = (const float*)d_in[10];
    float* out = (float*)d_out;

    k_pre<<<CNT_BLKS + TRN_BLKS, 256>>>(ei, Wl, Wr);           // 0: count + transpose
    k_scan<<<1, 1024>>>();                                     // 1: rowptr (+deg re-zero)
    k_mid<<<CNT_BLKS + PROJ_BLKS, 256>>>(ei, x, bl, br);       // 2: scatter + proj layer 0
    k_gat<<<NN / 8, 256>>>(att, cb, 0);                        // 3: <- PROFILED
    k_colstats<<<296, 256>>>(0);
    k_finalize<<<1, 64>>>(gw, gs, gb, 0);

    for (int l = 1; l < LLAY; ++l) {
        k_proj<<<PROJ_BLKS, 256>>>(x, bl, br, l);
        k_gat<<<NN / 8, 256>>>(att, cb, l);
        k_colstats<<<296, 256>>>(l);
        k_finalize<<<1, 64>>>(gw, gs, gb, l);
    }
    k_norm<<<296, 256>>>(out);
}